// round 3
// baseline (speedup 1.0000x reference)
#include <cuda_runtime.h>
#include <cuda_bf16.h>

#define BH_ 64
#define KP_ 512
#define NN_ 4096
#define DD_ 64
#define KT_ 64
#define TN_ 64
#define SROW_ 68   // padded row stride (floats) for 128b-aligned vector LDS

__device__ float g_z[BH_ * NN_];

__device__ __forceinline__ void fma2(unsigned long long &c, unsigned long long a, unsigned long long b) {
    asm("fma.rn.f32x2 %0, %1, %2, %0;" : "+l"(c) : "l"(a), "l"(b));
}
__device__ __forceinline__ float2 up2(unsigned long long u) {
    float2 r; asm("mov.b64 {%0, %1}, %2;" : "=f"(r.x), "=f"(r.y) : "l"(u)); return r;
}
__device__ __forceinline__ unsigned long long pk2(float x, float y) {
    unsigned long long u; asm("mov.b64 %0, {%1, %2};" : "=l"(u) : "f"(x), "f"(y)); return u;
}

// ---------------------------------------------------------------------------
// Kernel 1: z[bh,n] = sum_k exp(K[bh,k,:] . xk[bh,n,:])
// grid (BH, NN/256), 256 threads; one column per thread, x held in registers
// (packed f32x2), K chunks staged in smem and broadcast.
// ---------------------------------------------------------------------------
__global__ __launch_bounds__(256) void hm_zk(const float* __restrict__ K,
                                             const float* __restrict__ xk) {
    int bh = blockIdx.x;
    int n  = blockIdx.y * 256 + threadIdx.x;
    const float* Kb = K  + (size_t)bh * KP_ * DD_;
    const float* xr = xk + (size_t)bh * NN_ * DD_ + (size_t)n * DD_;

    unsigned long long x2[32];
#pragma unroll
    for (int i = 0; i < 16; i++) {
        float4 v = ((const float4*)xr)[i];
        x2[2*i]   = pk2(v.x, v.y);
        x2[2*i+1] = pk2(v.z, v.w);
    }

    __shared__ float Ks[64 * 64];
    float z = 0.f;
    for (int kc = 0; kc < KP_; kc += 64) {
        __syncthreads();
#pragma unroll
        for (int i = 0; i < 4; i++)
            ((float4*)Ks)[threadIdx.x + i * 256] =
                ((const float4*)(Kb + kc * DD_))[threadIdx.x + i * 256];
        __syncthreads();
#pragma unroll 2
        for (int kk = 0; kk < 64; kk++) {
            unsigned long long s0 = 0ull, s1 = 0ull, s2 = 0ull, s3 = 0ull;
            const ulonglong2* kr = (const ulonglong2*)(Ks + kk * 64);
#pragma unroll
            for (int d4 = 0; d4 < 16; d4 += 2) {
                ulonglong2 kv0 = kr[d4];
                ulonglong2 kv1 = kr[d4 + 1];
                fma2(s0, kv0.x, x2[2*d4]);
                fma2(s1, kv0.y, x2[2*d4+1]);
                fma2(s2, kv1.x, x2[2*d4+2]);
                fma2(s3, kv1.y, x2[2*d4+3]);
            }
            float2 a = up2(s0), b = up2(s1), c = up2(s2), d = up2(s3);
            float dist = ((a.x + a.y) + (b.x + b.y)) + ((c.x + c.y) + (d.x + d.y));
            z += __expf(dist);
        }
    }
    g_z[(size_t)bh * NN_ + n] = z;
}

// ---------------------------------------------------------------------------
// Kernel 2: block = (bh, 64-row k-slice). Streams N in 64-col tiles:
//   GEMM-A: dists[64,64] = Kslice @ xk_tile^T   (register tiled 4k x 4n)
//   epilogue: w = exp(dist) * (1/z[n]) -> smem; S[k] partials in regs
//   GEMM-B: accK/accV[64,64] += w @ {xk,xv}_tile (register accum 4k x 4d, f32x2)
// Final: gK = accK/S - K, gV = accV/S - V written directly (block-exclusive).
// ---------------------------------------------------------------------------
__global__ __launch_bounds__(256) void hm_mk(const float* __restrict__ K,
                                             const float* __restrict__ V,
                                             const float* __restrict__ xk,
                                             const float* __restrict__ xv,
                                             float* __restrict__ out) {
    extern __shared__ float sm[];
    float* sK  = sm;                      // [KT_][SROW_]
    float* sxk = sK  + KT_ * SROW_;       // [TN_][SROW_]
    float* sxv = sxk + TN_ * SROW_;       // [TN_][SROW_]
    float* sw  = sxv + TN_ * SROW_;       // [KT_][SROW_]  (w, later aliased for S-reduce)
    float* szr = sw  + KT_ * SROW_;       // [TN_] reciprocal z
    float* sS  = szr + TN_;               // [KT_] reciprocal S

    int bh  = blockIdx.x;
    int k0  = blockIdx.y * KT_;
    int tid = threadIdx.x;
    int kt  = tid >> 4;     // 0..15 -> k rows [4kt, 4kt+4)
    int nt  = tid & 15;     // 0..15 -> n cols [4nt, 4nt+4) (GEMM-A) / d cols (GEMM-B)

    const float* Kb  = K  + (size_t)bh * KP_ * DD_ + (size_t)k0 * DD_;
    const float* Vb  = V  + (size_t)bh * KP_ * DD_ + (size_t)k0 * DD_;
    const float* xkb = xk + (size_t)bh * NN_ * DD_;
    const float* xvb = xv + (size_t)bh * NN_ * DD_;
    const float* zb  = g_z + (size_t)bh * NN_;

    // Load K slice (64x64) into padded smem, resident for the whole block.
#pragma unroll
    for (int t = 0; t < 4; t++) {
        int f = tid + t * 256;          // float4 index, 1024 total
        int r = f >> 4, c = f & 15;
        *(float4*)&sK[r * SROW_ + c * 4] = ((const float4*)Kb)[f];
    }

    unsigned long long aK[4][2], aV[4][2];
#pragma unroll
    for (int i = 0; i < 4; i++) { aK[i][0]=aK[i][1]=aV[i][0]=aV[i][1]=0ull; }
    float sloc[4] = {0.f, 0.f, 0.f, 0.f};

#pragma unroll 1
    for (int n0 = 0; n0 < NN_; n0 += TN_) {
        __syncthreads();   // previous tile's sxk/sxv/sw fully consumed
#pragma unroll
        for (int t = 0; t < 4; t++) {
            int f = tid + t * 256;
            int r = f >> 4, c = f & 15;
            *(float4*)&sxk[r * SROW_ + c * 4] = ((const float4*)(xkb + (size_t)n0 * DD_))[f];
            *(float4*)&sxv[r * SROW_ + c * 4] = ((const float4*)(xvb + (size_t)n0 * DD_))[f];
        }
        if (tid < TN_) szr[tid] = 1.0f / zb[n0 + tid];
        __syncthreads();

        // ---- GEMM-A: dists (4k x 4n per thread), packed along d ----
        unsigned long long c2[4][4];
#pragma unroll
        for (int i = 0; i < 4; i++)
#pragma unroll
            for (int j = 0; j < 4; j++) c2[i][j] = 0ull;

        const float* kbase = sK  + (4 * kt) * SROW_;
        const float* xbase = sxk + (4 * nt) * SROW_;
#pragma unroll 4
        for (int d = 0; d < DD_; d += 4) {
            ulonglong2 a[4], b[4];
#pragma unroll
            for (int i = 0; i < 4; i++) a[i] = *(const ulonglong2*)(kbase + i * SROW_ + d);
#pragma unroll
            for (int j = 0; j < 4; j++) b[j] = *(const ulonglong2*)(xbase + j * SROW_ + d);
#pragma unroll
            for (int i = 0; i < 4; i++)
#pragma unroll
                for (int j = 0; j < 4; j++) {
                    fma2(c2[i][j], a[i].x, b[j].x);
                    fma2(c2[i][j], a[i].y, b[j].y);
                }
        }

        // ---- epilogue: w = exp(dist) / z[n], write to sw, accumulate S ----
        float rz0 = szr[4*nt], rz1 = szr[4*nt+1], rz2 = szr[4*nt+2], rz3 = szr[4*nt+3];
#pragma unroll
        for (int i = 0; i < 4; i++) {
            float2 p0 = up2(c2[i][0]); float w0 = __expf(p0.x + p0.y) * rz0;
            float2 p1 = up2(c2[i][1]); float w1 = __expf(p1.x + p1.y) * rz1;
            float2 p2 = up2(c2[i][2]); float w2 = __expf(p2.x + p2.y) * rz2;
            float2 p3 = up2(c2[i][3]); float w3 = __expf(p3.x + p3.y) * rz3;
            sloc[i] += (w0 + w1) + (w2 + w3);
            *(float4*)&sw[(4 * kt + i) * SROW_ + 4 * nt] = make_float4(w0, w1, w2, w3);
        }
        __syncthreads();

        // ---- GEMM-B: accK/accV += w @ x, packed along d ----
        const float* wbase = sw  + (4 * kt) * SROW_;
        const float* xka   = sxk + 4 * nt;
        const float* xva   = sxv + 4 * nt;
#pragma unroll 2
        for (int n = 0; n < TN_; n += 4) {
            float4 wv[4];
#pragma unroll
            for (int i = 0; i < 4; i++) wv[i] = *(const float4*)(wbase + i * SROW_ + n);
#pragma unroll
            for (int q = 0; q < 4; q++) {
                ulonglong2 bk = *(const ulonglong2*)(xka + (n + q) * SROW_);
                ulonglong2 bv = *(const ulonglong2*)(xva + (n + q) * SROW_);
#pragma unroll
                for (int i = 0; i < 4; i++) {
                    float wq = (q == 0) ? wv[i].x : (q == 1) ? wv[i].y : (q == 2) ? wv[i].z : wv[i].w;
                    unsigned long long wd = pk2(wq, wq);
                    fma2(aK[i][0], wd, bk.x);
                    fma2(aK[i][1], wd, bk.y);
                    fma2(aV[i][0], wd, bv.x);
                    fma2(aV[i][1], wd, bv.y);
                }
            }
        }
    }

    // ---- S reduction across the 16 nt-groups (alias sw as [16][KT_]) ----
    __syncthreads();
    *(float4*)&sw[nt * KT_ + 4 * kt] = make_float4(sloc[0], sloc[1], sloc[2], sloc[3]);
    __syncthreads();
    if (tid < KT_) {
        float s = 0.f;
#pragma unroll
        for (int r = 0; r < 16; r++) s += sw[r * KT_ + tid];
        sS[tid] = 1.0f / s;
    }
    __syncthreads();

    // ---- finalize: gK = accK/S - K, gV = accV/S - V ----
    size_t obase = (size_t)bh * KP_ * DD_ + (size_t)k0 * DD_;
    float* outK = out + obase;
    float* outV = out + (size_t)BH_ * KP_ * DD_ + obase;
#pragma unroll
    for (int i = 0; i < 4; i++) {
        int kk = 4 * kt + i;
        float rs = sS[kk];
        float2 k01 = up2(aK[i][0]), k23 = up2(aK[i][1]);
        float2 v01 = up2(aV[i][0]), v23 = up2(aV[i][1]);
        int off = kk * DD_ + 4 * nt;
        float4 kv = *(const float4*)&Kb[off];
        float4 vv = *(const float4*)&Vb[off];
        *(float4*)&outK[off] = make_float4(k01.x * rs - kv.x, k01.y * rs - kv.y,
                                           k23.x * rs - kv.z, k23.y * rs - kv.w);
        *(float4*)&outV[off] = make_float4(v01.x * rs - vv.x, v01.y * rs - vv.y,
                                           v23.x * rs - vv.z, v23.y * rs - vv.w);
    }
}

extern "C" void kernel_launch(void* const* d_in, const int* in_sizes, int n_in,
                              void* d_out, int out_size) {
    (void)in_sizes; (void)n_in; (void)out_size;
    const float* K  = (const float*)d_in[0];
    const float* V  = (const float*)d_in[1];
    const float* xk = (const float*)d_in[2];
    const float* xv = (const float*)d_in[3];
    float* out = (float*)d_out;

    const int smem_bytes = (KT_ * SROW_ + 2 * TN_ * SROW_ + KT_ * SROW_ + TN_ + KT_) * 4;
    cudaFuncSetAttribute(hm_mk, cudaFuncAttributeMaxDynamicSharedMemorySize, smem_bytes);

    hm_zk<<<dim3(BH_, NN_ / 256), 256>>>(K, xk);
    hm_mk<<<dim3(BH_, KP_ / KT_), 256, smem_bytes>>>(K, V, xk, xv, out);
}

// round 6
// speedup vs baseline: 4.0886x; 4.0886x over previous
#include <cuda_runtime.h>
#include <cuda_bf16.h>
#include <stdint.h>

#define BH 64
#define KP 512
#define NN 4096
#define DD 64

#define XSTR 144                 // bf16 tile row stride bytes (64 bf16 = 128B + 16B pad)
#define TILEB (128 * XSTR)       // 18432
#define WSTR 272                 // w tile row stride bytes (128 bf16 = 256B + 16B pad)
#define WTILEB (128 * WSTR)      // 34816

// pass-2 smem layout (bytes)
#define P2_KHI 0
#define P2_KLO 18432
#define P2_XKHI 36864
#define P2_XKLO 55296
#define P2_XVHI 73728
#define P2_XVLO 92160
#define P2_WHI 110592
#define P2_WLO 145408
#define P2_RZ 180224
#define P2_SP 180736
#define P2_RS 182784
#define P2_SMEM 183296

// pass-1 smem layout
#define P1_KHI 0
#define P1_KLO 18432
#define P1_XHI 36864
#define P1_XLO 55296
#define P1_ZP 73728
#define P1_SMEM 74752

__device__ float g_z[BH * NN];

// ---------------------------------------------------------------- helpers
__device__ __forceinline__ uint32_t s2u(const void* p) {
    return (uint32_t)__cvta_generic_to_shared(p);
}
__device__ __forceinline__ void mma_bf16(float* c, const uint32_t* a, const uint32_t* b) {
    asm volatile(
        "mma.sync.aligned.m16n8k16.row.col.f32.bf16.bf16.f32 "
        "{%0,%1,%2,%3}, {%4,%5,%6,%7}, {%8,%9}, {%0,%1,%2,%3};"
        : "+f"(c[0]), "+f"(c[1]), "+f"(c[2]), "+f"(c[3])
        : "r"(a[0]), "r"(a[1]), "r"(a[2]), "r"(a[3]), "r"(b[0]), "r"(b[1]));
}
__device__ __forceinline__ void ldsm4(uint32_t* r, uint32_t addr) {
    asm volatile("ldmatrix.sync.aligned.m8n8.x4.shared.b16 {%0,%1,%2,%3}, [%4];"
        : "=r"(r[0]), "=r"(r[1]), "=r"(r[2]), "=r"(r[3]) : "r"(addr));
}
__device__ __forceinline__ void ldsm4t(uint32_t* r, uint32_t addr) {
    asm volatile("ldmatrix.sync.aligned.m8n8.x4.trans.shared.b16 {%0,%1,%2,%3}, [%4];"
        : "=r"(r[0]), "=r"(r[1]), "=r"(r[2]), "=r"(r[3]) : "r"(addr));
}
__device__ __forceinline__ void split_store(float4 v, char* hip, char* lop) {
    __nv_bfloat162 h0 = __floats2bfloat162_rn(v.x, v.y);
    __nv_bfloat162 h1 = __floats2bfloat162_rn(v.z, v.w);
    float2 f0 = __bfloat1622float2(h0), f1 = __bfloat1622float2(h1);
    __nv_bfloat162 l0 = __floats2bfloat162_rn(v.x - f0.x, v.y - f0.y);
    __nv_bfloat162 l1 = __floats2bfloat162_rn(v.z - f1.x, v.w - f1.y);
    uint2 hw, lw;
    hw.x = *(uint32_t*)&h0; hw.y = *(uint32_t*)&h1;
    lw.x = *(uint32_t*)&l0; lw.y = *(uint32_t*)&l1;
    *(uint2*)hip = hw;
    *(uint2*)lop = lw;
}
// 128x64 fp32 tile -> hi/lo bf16 smem tiles (row stride XSTR). 256 threads.
__device__ __forceinline__ void load_split(const float4* __restrict__ src,
                                           char* hi, char* lo, int tid) {
#pragma unroll
    for (int j = 0; j < 8; j++) {
        int c = tid + j * 256;              // 2048 float4 chunks
        int row = c >> 4, cc = c & 15;
        float4 v = src[c];
        int off = row * XSTR + cc * 8;
        split_store(v, hi + off, lo + off);
    }
}

// GEMM-A: C[4 mb][4 j][4] += (Khi+Klo)[64k x 64d] @ (xhi+xlo)[32n x 64d]^T
// 3-term split. Warp tile (kw*64 rows, nw*32 cols). C row = t/4 (+8), col = (t%4)*2.
__device__ __forceinline__ void gemmA(float C[4][4][4],
        uint32_t uKhi, uint32_t uKlo, uint32_t uXhi, uint32_t uXlo,
        int kw, int nw, int lane) {
    const uint32_t arow = (uint32_t)(kw * 64 + (lane & 15)) * XSTR + (lane >> 4) * 16;
    const uint32_t brow = (uint32_t)(nw * 32 + (lane >> 4) * 8 + (lane & 7)) * XSTR
                        + ((lane >> 3) & 1) * 16;
#pragma unroll
    for (int kc = 0; kc < 4; kc++) {
        uint32_t ah[4][4], al[4][4], bh2[2][4], bl2[2][4];
#pragma unroll
        for (int mb = 0; mb < 4; mb++) {
            ldsm4(ah[mb], uKhi + arow + mb * (16 * XSTR) + kc * 32);
            ldsm4(al[mb], uKlo + arow + mb * (16 * XSTR) + kc * 32);
        }
#pragma unroll
        for (int g = 0; g < 2; g++) {
            ldsm4(bh2[g], uXhi + brow + g * (16 * XSTR) + kc * 32);
            ldsm4(bl2[g], uXlo + brow + g * (16 * XSTR) + kc * 32);
        }
#pragma unroll
        for (int mb = 0; mb < 4; mb++)
#pragma unroll
            for (int g = 0; g < 2; g++)
#pragma unroll
                for (int nbb = 0; nbb < 2; nbb++) {
                    float* c = C[mb][g * 2 + nbb];
                    mma_bf16(c, ah[mb], &bh2[g][nbb * 2]);   // hi*hi
                    mma_bf16(c, ah[mb], &bl2[g][nbb * 2]);   // hi*lo
                    mma_bf16(c, al[mb], &bh2[g][nbb * 2]);   // lo*hi
                }
    }
}

// ---------------------------------------------------------------- pass 1
// grid (32 n-tiles, 64 bh), 256 thr: z[n] = sum_k exp(K[k,:].xk[n,:])
__global__ __launch_bounds__(256) void hm_z(const float* __restrict__ K,
                                            const float* __restrict__ xk) {
    extern __shared__ char sm[];
    const int tid = threadIdx.x, lane = tid & 31, wid = tid >> 5;
    const int kw = wid >> 2, nw = wid & 3;
    const int n0 = blockIdx.x * 128, bh = blockIdx.y;
    char* sKhi = sm + P1_KHI; char* sKlo = sm + P1_KLO;
    char* sXhi = sm + P1_XHI; char* sXlo = sm + P1_XLO;
    float* zp = (float*)(sm + P1_ZP);
    const uint32_t uKhi = s2u(sKhi), uKlo = s2u(sKlo), uXhi = s2u(sXhi), uXlo = s2u(sXlo);

    load_split((const float4*)(xk + ((size_t)bh * NN + n0) * DD), sXhi, sXlo, tid);

    float zl[8];
#pragma unroll
    for (int i = 0; i < 8; i++) zl[i] = 0.f;

    for (int kt = 0; kt < 4; kt++) {
        __syncthreads();
        load_split((const float4*)(K + ((size_t)bh * KP + kt * 128) * DD), sKhi, sKlo, tid);
        __syncthreads();
        float C[4][4][4];
#pragma unroll
        for (int a = 0; a < 4; a++)
#pragma unroll
            for (int b = 0; b < 4; b++)
#pragma unroll
                for (int c = 0; c < 4; c++) C[a][b][c] = 0.f;
        gemmA(C, uKhi, uKlo, uXhi, uXlo, kw, nw, lane);
#pragma unroll
        for (int mb = 0; mb < 4; mb++)
#pragma unroll
            for (int j = 0; j < 4; j++) {
                zl[2 * j]     += __expf(C[mb][j][0]) + __expf(C[mb][j][2]);
                zl[2 * j + 1] += __expf(C[mb][j][1]) + __expf(C[mb][j][3]);
            }
    }
#pragma unroll
    for (int i = 0; i < 8; i++) {
        zl[i] += __shfl_xor_sync(~0u, zl[i], 4);
        zl[i] += __shfl_xor_sync(~0u, zl[i], 8);
        zl[i] += __shfl_xor_sync(~0u, zl[i], 16);
    }
    if (lane < 4) {
#pragma unroll
        for (int j = 0; j < 4; j++)
            *(float2*)&zp[kw * 128 + nw * 32 + j * 8 + lane * 2] =
                make_float2(zl[2 * j], zl[2 * j + 1]);
    }
    __syncthreads();
    if (tid < 128)
        g_z[(size_t)bh * NN + n0 + tid] = zp[tid] + zp[128 + tid];
}

// ---------------------------------------------------------------- pass 2
// grid (4 k-tiles, 64 bh), 256 thr. Streams 32 n-tiles of 128.
__global__ __launch_bounds__(256) void hm_main(const float* __restrict__ K,
        const float* __restrict__ V, const float* __restrict__ xk,
        const float* __restrict__ xv, float* __restrict__ out) {
    extern __shared__ char sm[];
    const int tid = threadIdx.x, lane = tid & 31, wid = tid >> 5;
    const int kw = wid >> 2, nw = wid & 3;    // nw doubles as dw in GEMM-B
    const int k0 = blockIdx.x * 128, bh = blockIdx.y;
    char* sKhi = sm + P2_KHI;   char* sKlo = sm + P2_KLO;
    char* sXKhi = sm + P2_XKHI; char* sXKlo = sm + P2_XKLO;
    char* sXVhi = sm + P2_XVHI; char* sXVlo = sm + P2_XVLO;
    char* sWhi = sm + P2_WHI;   char* sWlo = sm + P2_WLO;
    float* rz = (float*)(sm + P2_RZ);
    float* sp = (float*)(sm + P2_SP);
    float* rs = (float*)(sm + P2_RS);
    const uint32_t uKhi = s2u(sKhi), uKlo = s2u(sKlo);
    const uint32_t uXKhi = s2u(sXKhi), uXKlo = s2u(sXKlo);
    const uint32_t uXVhi = s2u(sXVhi), uXVlo = s2u(sXVlo);
    const uint32_t uWhi = s2u(sWhi), uWlo = s2u(sWlo);

    load_split((const float4*)(K + ((size_t)bh * KP + k0) * DD), sKhi, sKlo, tid);

    float accK[4][2][4], accV[4][2][4], sloc[8];
#pragma unroll
    for (int a = 0; a < 4; a++)
#pragma unroll
        for (int b = 0; b < 2; b++)
#pragma unroll
            for (int c = 0; c < 4; c++) { accK[a][b][c] = 0.f; accV[a][b][c] = 0.f; }
#pragma unroll
    for (int i = 0; i < 8; i++) sloc[i] = 0.f;

    // GEMM-B addressing
    const uint32_t aW = (uint32_t)(kw * 64 + (lane & 15)) * WSTR + (lane >> 4) * 16;
    const uint32_t bT = (uint32_t)(((lane >> 3) & 1) * 8 + (lane & 7)) * XSTR
                      + nw * 32 + (lane >> 4) * 16;

    for (int it = 0; it < NN / 128; it++) {
        const int n0 = it * 128;
        __syncthreads();   // prev iter's x/w tiles fully consumed
        load_split((const float4*)(xk + ((size_t)bh * NN + n0) * DD), sXKhi, sXKlo, tid);
        load_split((const float4*)(xv + ((size_t)bh * NN + n0) * DD), sXVhi, sXVlo, tid);
        if (tid < 128) rz[tid] = 1.0f / g_z[(size_t)bh * NN + n0 + tid];
        __syncthreads();

        // ---- GEMM-A: dists (3-term split) ----
        float C[4][4][4];
#pragma unroll
        for (int a = 0; a < 4; a++)
#pragma unroll
            for (int b = 0; b < 4; b++)
#pragma unroll
                for (int c = 0; c < 4; c++) C[a][b][c] = 0.f;
        gemmA(C, uKhi, uKlo, uXKhi, uXKlo, kw, nw, lane);

        // ---- epilogue: w = exp(d)*rz -> split -> smem; S partial ----
#pragma unroll
        for (int mb = 0; mb < 4; mb++)
#pragma unroll
            for (int j = 0; j < 4; j++)
#pragma unroll
                for (int rg = 0; rg < 2; rg++) {
                    int n = nw * 32 + j * 8 + (lane & 3) * 2;
                    int k = kw * 64 + mb * 16 + rg * 8 + (lane >> 2);
                    float w0 = __expf(C[mb][j][rg * 2])     * rz[n];
                    float w1 = __expf(C[mb][j][rg * 2 + 1]) * rz[n + 1];
                    sloc[mb * 2 + rg] += w0 + w1;
                    __nv_bfloat162 hp = __floats2bfloat162_rn(w0, w1);
                    float2 hf = __bfloat1622float2(hp);
                    __nv_bfloat162 lp = __floats2bfloat162_rn(w0 - hf.x, w1 - hf.y);
                    *(uint32_t*)(sWhi + k * WSTR + n * 2) = *(uint32_t*)&hp;
                    *(uint32_t*)(sWlo + k * WSTR + n * 2) = *(uint32_t*)&lp;
                }
        __syncthreads();   // w visible

        // ---- GEMM-B: accK += w @ xk, accV += w @ xv (contraction n, 3 terms) ----
#pragma unroll
        for (int ks = 0; ks < 8; ks++) {
            uint32_t awh[4][4], awl[4][4];
#pragma unroll
            for (int mb = 0; mb < 4; mb++) {
                ldsm4(awh[mb], uWhi + aW + mb * (16 * WSTR) + ks * 32);
                ldsm4(awl[mb], uWlo + aW + mb * (16 * WSTR) + ks * 32);
            }
            uint32_t bkh[4], bkl[4], bvh[4], bvl[4];
            ldsm4t(bkh, uXKhi + bT + ks * (16 * XSTR));
            ldsm4t(bkl, uXKlo + bT + ks * (16 * XSTR));
            ldsm4t(bvh, uXVhi + bT + ks * (16 * XSTR));
            ldsm4t(bvl, uXVlo + bT + ks * (16 * XSTR));
#pragma unroll
            for (int mb = 0; mb < 4; mb++)
#pragma unroll
                for (int g = 0; g < 2; g++) {
                    float* cK = accK[mb][g];
                    float* cV = accV[mb][g];
                    mma_bf16(cK, awh[mb], &bkh[g * 2]);
                    mma_bf16(cK, awh[mb], &bkl[g * 2]);
                    mma_bf16(cK, awl[mb], &bkh[g * 2]);
                    mma_bf16(cV, awh[mb], &bvh[g * 2]);
                    mma_bf16(cV, awh[mb], &bvl[g * 2]);
                    mma_bf16(cV, awl[mb], &bvh[g * 2]);
                }
        }
    }

    // ---- S reduction: quad shfl + across the 4 nw warps via smem ----
#pragma unroll
    for (int i = 0; i < 8; i++) {
        sloc[i] += __shfl_xor_sync(~0u, sloc[i], 1);
        sloc[i] += __shfl_xor_sync(~0u, sloc[i], 2);
    }
    __syncthreads();
    if ((lane & 3) == 0) {
#pragma unroll
        for (int mb = 0; mb < 4; mb++)
#pragma unroll
            for (int rg = 0; rg < 2; rg++) {
                int k = kw * 64 + mb * 16 + rg * 8 + (lane >> 2);
                sp[nw * 128 + k] = sloc[mb * 2 + rg];
            }
    }
    __syncthreads();
    if (tid < 128)
        rs[tid] = 1.0f / (sp[tid] + sp[128 + tid] + sp[256 + tid] + sp[384 + tid]);
    __syncthreads();

    // ---- finalize: gK = accK*rs - K, gV = accV*rs - V ----
#pragma unroll
    for (int mb = 0; mb < 4; mb++)
#pragma unroll
        for (int g = 0; g < 2; g++)
#pragma unroll
            for (int rg = 0; rg < 2; rg++) {
                int k = kw * 64 + mb * 16 + rg * 8 + (lane >> 2);
                int d = nw * 16 + g * 8 + (lane & 3) * 2;
                float r = rs[k];
                size_t gi = ((size_t)bh * KP + k0 + k) * DD + d;
                float2 kv = *(const float2*)(K + gi);
                float2 vv = *(const float2*)(V + gi);
                float2 ok, ov;
                ok.x = accK[mb][g][rg * 2]     * r - kv.x;
                ok.y = accK[mb][g][rg * 2 + 1] * r - kv.y;
                ov.x = accV[mb][g][rg * 2]     * r - vv.x;
                ov.y = accV[mb][g][rg * 2 + 1] * r - vv.y;
                *(float2*)(out + gi) = ok;
                *(float2*)(out + (size_t)BH * KP * DD + gi) = ov;
            }
}

// ---------------------------------------------------------------- launch
extern "C" void kernel_launch(void* const* d_in, const int* in_sizes, int n_in,
                              void* d_out, int out_size) {
    (void)in_sizes; (void)n_in; (void)out_size;
    const float* K  = (const float*)d_in[0];
    const float* V  = (const float*)d_in[1];
    const float* xk = (const float*)d_in[2];
    const float* xv = (const float*)d_in[3];
    float* out = (float*)d_out;

    cudaFuncSetAttribute(hm_z,    cudaFuncAttributeMaxDynamicSharedMemorySize, P1_SMEM);
    cudaFuncSetAttribute(hm_main, cudaFuncAttributeMaxDynamicSharedMemorySize, P2_SMEM);

    hm_z<<<dim3(NN / 128, BH), 256, P1_SMEM>>>(K, xk);
    hm_main<<<dim3(KP / 128, BH), 256, P2_SMEM>>>(K, V, xk, xv, out);
}

// round 7
// speedup vs baseline: 7.4343x; 1.8183x over previous
#include <cuda_runtime.h>
#include <cuda_bf16.h>
#include <stdint.h>

#define BH 64
#define KP 512
#define NN 4096
#define DD 64
#define XT 16384            // 128 x 64 bf16 tile, swizzled, 128B rows
#define WT 32768            // 128 x 128 bf16 tile, swizzled, 256B rows

// ---- hm_main smem layout (bytes) ----
#define M_X(b,c)  ((b) * 65536 + (c) * XT)   // c: 0=xkhi 1=xklo 2=xvhi 3=xvlo
#define M_KHI 131072
#define M_KLO 147456
#define M_WHI 163840
#define M_WLO 196608
#define M_RZ  229376        // 2 x 512B raw z values
#define M_SMEM 230400

// ---- hm_z smem layout ----
#define Z_XHI 0
#define Z_XLO XT
#define Z_K(b,c) (32768 + (b) * 32768 + (c) * XT)
#define Z_ZP 98304
#define Z_SMEM 99328

__device__ float g_z[BH * NN];
__device__ __align__(16) __nv_bfloat16 g_K_hi[BH * KP * DD];
__device__ __align__(16) __nv_bfloat16 g_K_lo[BH * KP * DD];
__device__ __align__(16) __nv_bfloat16 g_xk_hi[BH * NN * DD];
__device__ __align__(16) __nv_bfloat16 g_xk_lo[BH * NN * DD];
__device__ __align__(16) __nv_bfloat16 g_xv_hi[BH * NN * DD];
__device__ __align__(16) __nv_bfloat16 g_xv_lo[BH * NN * DD];

// ---------------------------------------------------------------- helpers
__device__ __forceinline__ uint32_t s2u(const void* p) {
    return (uint32_t)__cvta_generic_to_shared(p);
}
__device__ __forceinline__ void mma_bf16(float* c, const uint32_t* a, const uint32_t* b) {
    asm volatile(
        "mma.sync.aligned.m16n8k16.row.col.f32.bf16.bf16.f32 "
        "{%0,%1,%2,%3}, {%4,%5,%6,%7}, {%8,%9}, {%0,%1,%2,%3};"
        : "+f"(c[0]), "+f"(c[1]), "+f"(c[2]), "+f"(c[3])
        : "r"(a[0]), "r"(a[1]), "r"(a[2]), "r"(a[3]), "r"(b[0]), "r"(b[1]));
}
__device__ __forceinline__ void ldsm4(uint32_t* r, uint32_t addr) {
    asm volatile("ldmatrix.sync.aligned.m8n8.x4.shared.b16 {%0,%1,%2,%3}, [%4];"
        : "=r"(r[0]), "=r"(r[1]), "=r"(r[2]), "=r"(r[3]) : "r"(addr));
}
__device__ __forceinline__ void ldsm4t(uint32_t* r, uint32_t addr) {
    asm volatile("ldmatrix.sync.aligned.m8n8.x4.trans.shared.b16 {%0,%1,%2,%3}, [%4];"
        : "=r"(r[0]), "=r"(r[1]), "=r"(r[2]), "=r"(r[3]) : "r"(addr));
}
__device__ __forceinline__ void cpa(uint32_t dst, const void* src) {
    asm volatile("cp.async.cg.shared.global [%0], [%1], 16;" :: "r"(dst), "l"(src));
}
#define CPA_COMMIT() asm volatile("cp.async.commit_group;" ::: "memory")
__device__ __forceinline__ void cpa_wait1() { asm volatile("cp.async.wait_group 1;" ::: "memory"); }

// Copy one 128x64 bf16 tile (16KB) global -> swizzled smem (128B rows).
__device__ __forceinline__ void cpa_tile(uint32_t sbase, const __nv_bfloat16* g, int tid) {
#pragma unroll
    for (int j = 0; j < 4; j++) {
        int ch = tid + j * 256;                     // 0..1023 16B chunks
        int row = ch >> 3, c = ch & 7;
        uint32_t off = (uint32_t)row * 128 + (((uint32_t)c * 16) ^ (((uint32_t)row & 7) << 4));
        cpa(sbase + off, (const char*)g + (size_t)ch * 16);
    }
}

// GEMM-A: C[4 mb][4 j][4] += (Khi+Klo)[64k x 64d] @ (xhi+xlo)[32n x 64d]^T
// 3-term split, swizzled tiles, term-major MMA order (no same-acc back-to-back).
__device__ __forceinline__ void gemmA(float C[4][4][4],
        uint32_t uKhi, uint32_t uKlo, uint32_t uXhi, uint32_t uXlo,
        int kw, int nw, int lane) {
    const uint32_t sx = ((uint32_t)lane & 7) << 4;
    const uint32_t ar = (uint32_t)(kw * 64 + (lane & 15));
    const uint32_t br = (uint32_t)(nw * 32 + ((lane >> 4) & 1) * 8 + (lane & 7));
#pragma unroll
    for (int kc = 0; kc < 4; kc++) {
        const uint32_t acol = ((((uint32_t)lane >> 4) & 1) * 16 + kc * 32) ^ sx;
        const uint32_t bcol = ((((uint32_t)lane >> 3) & 1) * 16 + kc * 32) ^ sx;
        uint32_t ah[4][4], al[4][4], bh2[2][4], bl2[2][4];
#pragma unroll
        for (int mb = 0; mb < 4; mb++) {
            ldsm4(ah[mb], uKhi + (ar + mb * 16) * 128 + acol);
            ldsm4(al[mb], uKlo + (ar + mb * 16) * 128 + acol);
        }
#pragma unroll
        for (int g = 0; g < 2; g++) {
            ldsm4(bh2[g], uXhi + (br + g * 16) * 128 + bcol);
            ldsm4(bl2[g], uXlo + (br + g * 16) * 128 + bcol);
        }
#pragma unroll
        for (int mb = 0; mb < 4; mb++)
#pragma unroll
            for (int g = 0; g < 2; g++)
#pragma unroll
                for (int nbb = 0; nbb < 2; nbb++)
                    mma_bf16(C[mb][g * 2 + nbb], ah[mb], &bh2[g][nbb * 2]);   // hi*hi
#pragma unroll
        for (int mb = 0; mb < 4; mb++)
#pragma unroll
            for (int g = 0; g < 2; g++)
#pragma unroll
                for (int nbb = 0; nbb < 2; nbb++)
                    mma_bf16(C[mb][g * 2 + nbb], ah[mb], &bl2[g][nbb * 2]);   // hi*lo
#pragma unroll
        for (int mb = 0; mb < 4; mb++)
#pragma unroll
            for (int g = 0; g < 2; g++)
#pragma unroll
                for (int nbb = 0; nbb < 2; nbb++)
                    mma_bf16(C[mb][g * 2 + nbb], al[mb], &bh2[g][nbb * 2]);   // lo*hi
    }
}

// ---------------------------------------------------------------- split
__global__ __launch_bounds__(256) void hm_split(const float4* __restrict__ src, int which, int n4) {
    int i = blockIdx.x * 256 + threadIdx.x;
    if (i >= n4) return;
    __nv_bfloat16 *hi, *lo;
    if (which == 0)      { hi = g_K_hi;  lo = g_K_lo;  }
    else if (which == 1) { hi = g_xk_hi; lo = g_xk_lo; }
    else                 { hi = g_xv_hi; lo = g_xv_lo; }
    float4 v = src[i];
    __nv_bfloat162 h0 = __floats2bfloat162_rn(v.x, v.y);
    __nv_bfloat162 h1 = __floats2bfloat162_rn(v.z, v.w);
    float2 f0 = __bfloat1622float2(h0), f1 = __bfloat1622float2(h1);
    __nv_bfloat162 l0 = __floats2bfloat162_rn(v.x - f0.x, v.y - f0.y);
    __nv_bfloat162 l1 = __floats2bfloat162_rn(v.z - f1.x, v.w - f1.y);
    uint2 hw, lw;
    hw.x = *(uint32_t*)&h0; hw.y = *(uint32_t*)&h1;
    lw.x = *(uint32_t*)&l0; lw.y = *(uint32_t*)&l1;
    ((uint2*)hi)[i] = hw;
    ((uint2*)lo)[i] = lw;
}

// ---------------------------------------------------------------- pass 1: z
__global__ __launch_bounds__(256) void hm_z() {
    extern __shared__ char sm[];
    const int tid = threadIdx.x, lane = tid & 31, wid = tid >> 5;
    const int kw = wid >> 2, nw = wid & 3;
    const int n0 = blockIdx.x * 128, bh = blockIdx.y;
    uint32_t sb = s2u(sm);

    cpa_tile(sb + Z_XHI, g_xk_hi + ((size_t)bh * NN + n0) * DD, tid);
    cpa_tile(sb + Z_XLO, g_xk_lo + ((size_t)bh * NN + n0) * DD, tid);
    cpa_tile(sb + Z_K(0, 0), g_K_hi + (size_t)bh * KP * DD, tid);
    cpa_tile(sb + Z_K(0, 1), g_K_lo + (size_t)bh * KP * DD, tid);
    CPA_COMMIT();

    float zl[8];
#pragma unroll
    for (int i = 0; i < 8; i++) zl[i] = 0.f;

    for (int kt = 0; kt < 4; kt++) {
        if (kt + 1 < 4) {
            cpa_tile(sb + Z_K((kt + 1) & 1, 0), g_K_hi + ((size_t)bh * KP + (kt + 1) * 128) * DD, tid);
            cpa_tile(sb + Z_K((kt + 1) & 1, 1), g_K_lo + ((size_t)bh * KP + (kt + 1) * 128) * DD, tid);
        }
        CPA_COMMIT();
        cpa_wait1();
        __syncthreads();

        float C[4][4][4];
#pragma unroll
        for (int a = 0; a < 4; a++)
#pragma unroll
            for (int b = 0; b < 4; b++)
#pragma unroll
                for (int c = 0; c < 4; c++) C[a][b][c] = 0.f;
        gemmA(C, sb + Z_K(kt & 1, 0), sb + Z_K(kt & 1, 1), sb + Z_XHI, sb + Z_XLO, kw, nw, lane);
#pragma unroll
        for (int mb = 0; mb < 4; mb++)
#pragma unroll
            for (int j = 0; j < 4; j++) {
                zl[2 * j]     += __expf(C[mb][j][0]) + __expf(C[mb][j][2]);
                zl[2 * j + 1] += __expf(C[mb][j][1]) + __expf(C[mb][j][3]);
            }
        __syncthreads();   // readers done before next prefetch overwrites buffer
    }
#pragma unroll
    for (int i = 0; i < 8; i++) {
        zl[i] += __shfl_xor_sync(~0u, zl[i], 4);
        zl[i] += __shfl_xor_sync(~0u, zl[i], 8);
        zl[i] += __shfl_xor_sync(~0u, zl[i], 16);
    }
    float* zp = (float*)(sm + Z_ZP);
    if (lane < 4) {
#pragma unroll
        for (int j = 0; j < 4; j++)
            *(float2*)&zp[kw * 128 + nw * 32 + j * 8 + lane * 2] =
                make_float2(zl[2 * j], zl[2 * j + 1]);
    }
    __syncthreads();
    if (tid < 128)
        g_z[(size_t)bh * NN + n0 + tid] = zp[tid] + zp[128 + tid];
}

// ---------------------------------------------------------------- pass 2
__global__ __launch_bounds__(256) void hm_main(const float* __restrict__ K,
        const float* __restrict__ V, float* __restrict__ out) {
    extern __shared__ char sm[];
    const int tid = threadIdx.x, lane = tid & 31, wid = tid >> 5;
    const int kw = wid >> 2, nw = wid & 3;
    const int k0 = blockIdx.x * 128, bh = blockIdx.y;
    uint32_t sb = s2u(sm);
    const uint32_t sx = ((uint32_t)lane & 7) << 4;

    // prologue: K tiles + x(0) + z(0)
    cpa_tile(sb + M_KHI, g_K_hi + ((size_t)bh * KP + k0) * DD, tid);
    cpa_tile(sb + M_KLO, g_K_lo + ((size_t)bh * KP + k0) * DD, tid);
    cpa_tile(sb + M_X(0, 0), g_xk_hi + (size_t)bh * NN * DD, tid);
    cpa_tile(sb + M_X(0, 1), g_xk_lo + (size_t)bh * NN * DD, tid);
    cpa_tile(sb + M_X(0, 2), g_xv_hi + (size_t)bh * NN * DD, tid);
    cpa_tile(sb + M_X(0, 3), g_xv_lo + (size_t)bh * NN * DD, tid);
    if (tid < 32) cpa(sb + M_RZ + tid * 16, g_z + (size_t)bh * NN + tid * 4);
    CPA_COMMIT();

    float accK[4][2][4], accV[4][2][4], sloc[8];
#pragma unroll
    for (int a = 0; a < 4; a++)
#pragma unroll
        for (int b = 0; b < 2; b++)
#pragma unroll
            for (int c = 0; c < 4; c++) { accK[a][b][c] = 0.f; accV[a][b][c] = 0.f; }
#pragma unroll
    for (int i = 0; i < 8; i++) sloc[i] = 0.f;

    const uint32_t wr = (uint32_t)(kw * 64 + (lane & 15));
    const uint32_t xr = (uint32_t)(((lane >> 3) & 1) * 8 + (lane & 7));
    const uint32_t xcol = ((uint32_t)(nw * 32 + ((lane >> 4) & 1) * 16)) ^ sx;
    const uint32_t wsx = (((uint32_t)(lane >> 2) & 7)) << 4;

    for (int it = 0; it < NN / 128; it++) {
        const int b = it & 1;
        if (it + 1 < NN / 128) {
            const size_t n1 = (size_t)bh * NN + (size_t)(it + 1) * 128;
            cpa_tile(sb + M_X(b ^ 1, 0), g_xk_hi + n1 * DD, tid);
            cpa_tile(sb + M_X(b ^ 1, 1), g_xk_lo + n1 * DD, tid);
            cpa_tile(sb + M_X(b ^ 1, 2), g_xv_hi + n1 * DD, tid);
            cpa_tile(sb + M_X(b ^ 1, 3), g_xv_lo + n1 * DD, tid);
            if (tid < 32) cpa(sb + M_RZ + (b ^ 1) * 512 + tid * 16, g_z + n1 + tid * 4);
        }
        CPA_COMMIT();
        cpa_wait1();
        __syncthreads();

        // ---- GEMM-A: dists ----
        float C[4][4][4];
#pragma unroll
        for (int a = 0; a < 4; a++)
#pragma unroll
            for (int bb = 0; bb < 4; bb++)
#pragma unroll
                for (int c = 0; c < 4; c++) C[a][bb][c] = 0.f;
        gemmA(C, sb + M_KHI, sb + M_KLO, sb + M_X(b, 0), sb + M_X(b, 1), kw, nw, lane);

        // ---- epilogue: w = exp(d)/z -> split -> swizzled smem; S partials ----
        const float* zbuf = (const float*)(sm + M_RZ + b * 512);
        float rzv[8];
#pragma unroll
        for (int j = 0; j < 4; j++) {
            int n = nw * 32 + j * 8 + (lane & 3) * 2;
            rzv[2 * j]     = __fdividef(1.0f, zbuf[n]);
            rzv[2 * j + 1] = __fdividef(1.0f, zbuf[n + 1]);
        }
#pragma unroll
        for (int mb = 0; mb < 4; mb++)
#pragma unroll
            for (int j = 0; j < 4; j++)
#pragma unroll
                for (int rg = 0; rg < 2; rg++) {
                    int n = nw * 32 + j * 8 + (lane & 3) * 2;
                    int k = kw * 64 + mb * 16 + rg * 8 + (lane >> 2);
                    float w0 = __expf(C[mb][j][rg * 2])     * rzv[2 * j];
                    float w1 = __expf(C[mb][j][rg * 2 + 1]) * rzv[2 * j + 1];
                    sloc[mb * 2 + rg] += w0 + w1;
                    __nv_bfloat162 hp = __floats2bfloat162_rn(w0, w1);
                    float2 hf = __bfloat1622float2(hp);
                    __nv_bfloat162 lp = __floats2bfloat162_rn(w0 - hf.x, w1 - hf.y);
                    uint32_t co = ((uint32_t)(n * 2)) ^ wsx;
                    *(uint32_t*)(sm + M_WHI + (uint32_t)k * 256 + co) = *(uint32_t*)&hp;
                    *(uint32_t*)(sm + M_WLO + (uint32_t)k * 256 + co) = *(uint32_t*)&lp;
                }
        __syncthreads();

        // ---- GEMM-B: accK += w @ xk, accV += w @ xv ----
#pragma unroll
        for (int ks = 0; ks < 8; ks++) {
            const uint32_t wcol = ((((uint32_t)lane >> 4) & 1) * 16 + (uint32_t)ks * 32) ^ sx;
            uint32_t awh[4][4], awl[4][4];
#pragma unroll
            for (int mb = 0; mb < 4; mb++) {
                ldsm4(awh[mb], sb + M_WHI + (wr + mb * 16) * 256 + wcol);
                ldsm4(awl[mb], sb + M_WLO + (wr + mb * 16) * 256 + wcol);
            }
            uint32_t bkh[4], bkl[4], bvh[4], bvl[4];
            ldsm4t(bkh, sb + M_X(b, 0) + (xr + ks * 16) * 128 + xcol);
            ldsm4t(bkl, sb + M_X(b, 1) + (xr + ks * 16) * 128 + xcol);
            ldsm4t(bvh, sb + M_X(b, 2) + (xr + ks * 16) * 128 + xcol);
            ldsm4t(bvl, sb + M_X(b, 3) + (xr + ks * 16) * 128 + xcol);
#pragma unroll
            for (int mb = 0; mb < 4; mb++)
#pragma unroll
                for (int g = 0; g < 2; g++) {
                    mma_bf16(accK[mb][g], awh[mb], &bkh[g * 2]);
                    mma_bf16(accV[mb][g], awh[mb], &bvh[g * 2]);
                    mma_bf16(accK[mb][g], awh[mb], &bkl[g * 2]);
                    mma_bf16(accV[mb][g], awh[mb], &bvl[g * 2]);
                    mma_bf16(accK[mb][g], awl[mb], &bkh[g * 2]);
                    mma_bf16(accV[mb][g], awl[mb], &bvh[g * 2]);
                }
        }
        __syncthreads();   // readers done before next prefetch overwrites x buffer
    }

    // ---- S reduction (sp aliased onto W-hi, rs onto rz buffer 0) ----
#pragma unroll
    for (int i = 0; i < 8; i++) {
        sloc[i] += __shfl_xor_sync(~0u, sloc[i], 1);
        sloc[i] += __shfl_xor_sync(~0u, sloc[i], 2);
    }
    float* sp = (float*)(sm + M_WHI);
    float* rs = (float*)(sm + M_RZ);
    if ((lane & 3) == 0) {
#pragma unroll
        for (int mb = 0; mb < 4; mb++)
#pragma unroll
            for (int rg = 0; rg < 2; rg++) {
                int k = kw * 64 + mb * 16 + rg * 8 + (lane >> 2);
                sp[nw * 128 + k] = sloc[mb * 2 + rg];
            }
    }
    __syncthreads();
    if (tid < 128)
        rs[tid] = 1.0f / (sp[tid] + sp[128 + tid] + sp[256 + tid] + sp[384 + tid]);
    __syncthreads();

    // ---- finalize: gK = accK*rs - K, gV = accV*rs - V ----
#pragma unroll
    for (int mb = 0; mb < 4; mb++)
#pragma unroll
        for (int g = 0; g < 2; g++)
#pragma unroll
            for (int rg = 0; rg < 2; rg++) {
                int k = kw * 64 + mb * 16 + rg * 8 + (lane >> 2);
                int d = nw * 16 + g * 8 + (lane & 3) * 2;
                float r = rs[k];
                size_t gi = ((size_t)bh * KP + k0 + k) * DD + d;
                float2 kv = *(const float2*)(K + gi);
                float2 vv = *(const float2*)(V + gi);
                float2 ok, ov;
                ok.x = accK[mb][g][rg * 2]     * r - kv.x;
                ok.y = accK[mb][g][rg * 2 + 1] * r - kv.y;
                ov.x = accV[mb][g][rg * 2]     * r - vv.x;
                ov.y = accV[mb][g][rg * 2 + 1] * r - vv.y;
                *(float2*)(out + gi) = ok;
                *(float2*)(out + (size_t)BH * KP * DD + gi) = ov;
            }
}

// ---------------------------------------------------------------- launch
extern "C" void kernel_launch(void* const* d_in, const int* in_sizes, int n_in,
                              void* d_out, int out_size) {
    (void)in_sizes; (void)n_in; (void)out_size;
    const float* K  = (const float*)d_in[0];
    const float* V  = (const float*)d_in[1];
    const float* xk = (const float*)d_in[2];
    const float* xv = (const float*)d_in[3];
    float* out = (float*)d_out;

    cudaFuncSetAttribute(hm_z,    cudaFuncAttributeMaxDynamicSharedMemorySize, Z_SMEM);
    cudaFuncSetAttribute(hm_main, cudaFuncAttributeMaxDynamicSharedMemorySize, M_SMEM);

    hm_split<<<(BH * KP * DD / 4 + 255) / 256, 256>>>((const float4*)K,  0, BH * KP * DD / 4);
    hm_split<<<(BH * NN * DD / 4 + 255) / 256, 256>>>((const float4*)xk, 1, BH * NN * DD / 4);
    hm_split<<<(BH * NN * DD / 4 + 255) / 256, 256>>>((const float4*)xv, 2, BH * NN * DD / 4);
    hm_z<<<dim3(NN / 128, BH), 256, Z_SMEM>>>();
    hm_main<<<dim3(KP / 128, BH), 256, M_SMEM>>>(K, V, out);
}